// round 10
// baseline (speedup 1.0000x reference)
#include <cuda_runtime.h>
#include <math.h>

// ---------------------------------------------------------------------------
// ViTBlockQuantum, fully fused. Analytic collapse of the 8-qubit VQC:
//   phi_w = in_w + theta_w;  z_k = prod_{w=0..k} cos(phi_w) (k>=1),
//   z_0 = prod_{w=1..7} cos(phi_w)
// One kernel: block = (batch, query-half), 1024 threads.
//   phase 1: K (thr 0-255), V (256-511), Q (512-639), consts (640+)
//   phase 2: thread = (query-pair, head) x k-eighth with kh in LANE LOW BITS;
//            2 keys x 2 queries/iter f32x2; k-split reduced via SHFL.BFLY
//            (no Part smem, one fewer barrier)
//   phase 3: per-token tail on 8 warps x 16 lanes
// ---------------------------------------------------------------------------

#define EGS 8
#define SSEQ 256
#define QH 128
// 0.5 (1/sqrt(dk), dk=4) * log2(e): folded into Q so softmax uses ex2 directly
#define QSCALE 0.72134752044448170368f

typedef unsigned long long u64;

__device__ __forceinline__ float ex2f(float x) {
    float y; asm("ex2.approx.ftz.f32 %0, %1;" : "=f"(y) : "f"(x)); return y;
}
__device__ __forceinline__ u64 pk2(float lo, float hi) {
    u64 r; asm("mov.b64 %0, {%1, %2};" : "=l"(r) : "f"(lo), "f"(hi)); return r;
}
__device__ __forceinline__ void upk2(float& lo, float& hi, u64 v) {
    asm("mov.b64 {%0, %1}, %2;" : "=f"(lo), "=f"(hi) : "l"(v));
}
__device__ __forceinline__ u64 mul2(u64 a, u64 b) {
    u64 d; asm("mul.rn.f32x2 %0, %1, %2;" : "=l"(d) : "l"(a), "l"(b)); return d;
}
__device__ __forceinline__ u64 fma2(u64 a, u64 b, u64 c) {
    u64 d; asm("fma.rn.f32x2 %0, %1, %2, %3;" : "=l"(d) : "l"(a), "l"(b), "l"(c)); return d;
}
__device__ __forceinline__ u64 add2(u64 a, u64 b) {
    u64 d; asm("add.rn.f32x2 %0, %1, %2;" : "=l"(d) : "l"(a), "l"(b)); return d;
}

__device__ __forceinline__ void vqc8(const float a[8], float z[8]) {
    float c[8];
#pragma unroll
    for (int w = 0; w < 8; w++) c[w] = __cosf(a[w]);
    float p = c[0];
#pragma unroll
    for (int k = 1; k < 8; k++) { p *= c[k]; z[k] = p; }
    float q = c[1];
#pragma unroll
    for (int w = 2; w < 8; w++) q *= c[w];
    z[0] = q;
}

// paired K/V smem layout: keys 2k,2k+1 interleaved; key-pair kp = 4 ulonglong2:
//   u2#(kp*4 + h*2 + j) = packed (dim 2j, dim 2j+1) f32x2 pairs for head h
__device__ __forceinline__ int kvidx(int k, int d) {
    return (k >> 1) * 16 + (d >> 2) * 8 + ((d & 2) << 1) + ((d & 1) << 1) + (k & 1);
}

__global__ void __launch_bounds__(1024, 1) fused_kernel(
    const float* __restrict__ x,
    const float* __restrict__ Wq, const float* __restrict__ Wk,
    const float* __restrict__ Wv, const float* __restrict__ Wc,
    const float* __restrict__ Wf,
    const float* __restrict__ w1, const float* __restrict__ b1,
    const float* __restrict__ w2, const float* __restrict__ b2,
    const float* __restrict__ g1, const float* __restrict__ be1,
    const float* __restrict__ g2, const float* __restrict__ be2,
    float* __restrict__ out)
{
    __shared__ __align__(16) float Ks[SSEQ * 8];
    __shared__ __align__(16) float Vs[SSEQ * 8];
    __shared__ __align__(16) float Qs[QH * 8];
    __shared__ float Ctx[QH * 8];
    __shared__ float cw1[64], cw2[64];
    __shared__ float cb1[8], cb2[8], cwc[8], cwf[8];
    __shared__ float cg1[8], cbe1[8], cg2[8], cbe2[8];

    const int b   = blockIdx.x >> 1;
    const int qh  = blockIdx.x & 1;
    const int tid = threadIdx.x;

    // ---------------- phase 1: QKV + constant staging (parallel groups) ------
    if (tid < 512) {
        const int t = tid & 255;
        const int isV = tid >> 8;
        const float* W = isV ? Wv : Wk;
        const float4* xt = (const float4*)(x + (size_t)(b * SSEQ + t) * EGS);
        float4 x0 = xt[0], x1 = xt[1];
        float a[8], z[8];
        a[0] = x0.x + __ldg(W + 0); a[1] = x0.y + __ldg(W + 1);
        a[2] = x0.z + __ldg(W + 2); a[3] = x0.w + __ldg(W + 3);
        a[4] = x1.x + __ldg(W + 4); a[5] = x1.y + __ldg(W + 5);
        a[6] = x1.z + __ldg(W + 6); a[7] = x1.w + __ldg(W + 7);
        vqc8(a, z);
        float* dst = isV ? Vs : Ks;
#pragma unroll
        for (int d = 0; d < 8; d++) dst[kvidx(t, d)] = z[d];
    } else if (tid < 640) {
        const int i = tid - 512;
        const float4* xt = (const float4*)(x + (size_t)(b * SSEQ + qh * QH + i) * EGS);
        float4 x0 = xt[0], x1 = xt[1];
        float a[8], z[8];
        a[0] = x0.x + __ldg(Wq + 0); a[1] = x0.y + __ldg(Wq + 1);
        a[2] = x0.z + __ldg(Wq + 2); a[3] = x0.w + __ldg(Wq + 3);
        a[4] = x1.x + __ldg(Wq + 4); a[5] = x1.y + __ldg(Wq + 5);
        a[6] = x1.z + __ldg(Wq + 6); a[7] = x1.w + __ldg(Wq + 7);
        vqc8(a, z);
#pragma unroll
        for (int d = 0; d < 8; d++) Qs[i * 8 + d] = z[d] * QSCALE;
    } else {
        const int j = tid - 640;
        if (j < 64) { cw1[j] = w1[j]; cw2[j] = w2[j]; }
        else if (j < 72) {
            const int k = j - 64;
            cb1[k] = b1[k];  cb2[k] = b2[k];
            cwc[k] = Wc[k];  cwf[k] = Wf[k];
            cg1[k] = g1[k];  cbe1[k] = be1[k];
            cg2[k] = g2[k];  cbe2[k] = be2[k];
        }
    }
    __syncthreads();

    // ---------------- phase 2: attention, kh in lane low bits ----------------
    {
        const int kh = tid & 7;            // k-eighth (SHFL-reducible in-warp)
        const int u  = tid >> 3;           // (query-pair, head) unit 0..127
        const int qp = u >> 1;             // query pair (queries 2qp, 2qp+1)
        const int h  = u & 1;              // head

        float4 qA = *(const float4*)&Qs[(qp * 2) * 8 + h * 4];
        float4 qB = *(const float4*)&Qs[(qp * 2 + 1) * 8 + h * 4];
        u64 qA0 = pk2(qA.x, qA.x), qA1 = pk2(qA.y, qA.y);
        u64 qA2 = pk2(qA.z, qA.z), qA3 = pk2(qA.w, qA.w);
        u64 qB0 = pk2(qB.x, qB.x), qB1 = pk2(qB.y, qB.y);
        u64 qB2 = pk2(qB.z, qB.z), qB3 = pk2(qB.w, qB.w);

        const ulonglong2* Kp = (const ulonglong2*)Ks + (kh << 6) + (h << 1);
        const ulonglong2* Vp = (const ulonglong2*)Vs + (kh << 6) + (h << 1);

        u64 sumA = 0ull, a0 = 0ull, a1 = 0ull, a2 = 0ull, a3 = 0ull;
        u64 sumB = 0ull, b0 = 0ull, b1_ = 0ull, b2_ = 0ull, b3_ = 0ull;
#pragma unroll 8
        for (int kp = 0; kp < 16; kp++) {
            ulonglong2 kk0 = Kp[kp * 4], kk1 = Kp[kp * 4 + 1];
            u64 s0 = mul2(qA0, kk0.x);
            u64 s1 = mul2(qB0, kk0.x);
            s0 = fma2(qA1, kk0.y, s0);
            s1 = fma2(qB1, kk0.y, s1);
            s0 = fma2(qA2, kk1.x, s0);
            s1 = fma2(qB2, kk1.x, s1);
            s0 = fma2(qA3, kk1.y, s0);
            s1 = fma2(qB3, kk1.y, s1);
            float l0, h0, l1, h1;
            upk2(l0, h0, s0);
            upk2(l1, h1, s1);
            u64 pp0 = pk2(ex2f(l0), ex2f(h0));
            u64 pp1 = pk2(ex2f(l1), ex2f(h1));
            ulonglong2 vv0 = Vp[kp * 4], vv1 = Vp[kp * 4 + 1];
            sumA = add2(sumA, pp0);
            sumB = add2(sumB, pp1);
            a0 = fma2(pp0, vv0.x, a0);
            b0 = fma2(pp1, vv0.x, b0);
            a1 = fma2(pp0, vv0.y, a1);
            b1_ = fma2(pp1, vv0.y, b1_);
            a2 = fma2(pp0, vv1.x, a2);
            b2_ = fma2(pp1, vv1.x, b2_);
            a3 = fma2(pp0, vv1.y, a3);
            b3_ = fma2(pp1, vv1.y, b3_);
        }
        float cA[5], cB[5];
        { float l, hx; upk2(l, hx, sumA); cA[0] = l + hx; }
        { float l, hx; upk2(l, hx, a0);   cA[1] = l + hx; }
        { float l, hx; upk2(l, hx, a1);   cA[2] = l + hx; }
        { float l, hx; upk2(l, hx, a2);   cA[3] = l + hx; }
        { float l, hx; upk2(l, hx, a3);   cA[4] = l + hx; }
        { float l, hx; upk2(l, hx, sumB); cB[0] = l + hx; }
        { float l, hx; upk2(l, hx, b0);   cB[1] = l + hx; }
        { float l, hx; upk2(l, hx, b1_);  cB[2] = l + hx; }
        { float l, hx; upk2(l, hx, b2_);  cB[3] = l + hx; }
        { float l, hx; upk2(l, hx, b3_);  cB[4] = l + hx; }

        // in-warp reduction across the 8 k-eighths (lanes differ in low 3 bits)
#pragma unroll
        for (int m = 1; m <= 4; m <<= 1) {
#pragma unroll
            for (int j = 0; j < 5; j++) {
                cA[j] += __shfl_xor_sync(0xffffffffu, cA[j], m);
                cB[j] += __shfl_xor_sync(0xffffffffu, cB[j], m);
            }
        }
        if (kh == 0) {
            float invA = __fdividef(1.f, cA[0]);
            float invB = __fdividef(1.f, cB[0]);
            float* cxA = &Ctx[(qp * 2) * 8 + h * 4];
            float* cxB = &Ctx[(qp * 2 + 1) * 8 + h * 4];
            cxA[0] = cA[1] * invA; cxA[1] = cA[2] * invA;
            cxA[2] = cA[3] * invA; cxA[3] = cA[4] * invA;
            cxB[0] = cB[1] * invB; cxB[1] = cB[2] * invB;
            cxB[2] = cB[3] * invB; cxB[3] = cB[4] * invB;
        }
        __syncthreads();
    }

    // ------ phase 3: tail, 128 tokens on 8 warps x 16 lanes (2 warps/SMSP) ---
    const int lane = tid & 31;
    if (tid < 256 && lane < 16) {
        const int tl  = (tid >> 5) * 16 + lane;   // local token 0..127
        const int tok = b * SSEQ + qh * QH + tl;
        const float4* xt = (const float4*)(x + (size_t)tok * EGS);  // L1-warm
        float4 x0 = xt[0], x1 = xt[1];
        float xi[8] = {x0.x, x0.y, x0.z, x0.w, x1.x, x1.y, x1.z, x1.w};

        float a[8], ao[8];
#pragma unroll
        for (int w = 0; w < 8; w++) a[w] = Ctx[tl * 8 + w] + cwc[w];
        vqc8(a, ao);

        float y[8], m = 0.f;
#pragma unroll
        for (int w = 0; w < 8; w++) { y[w] = xi[w] + ao[w]; m += y[w]; }
        m *= 0.125f;
        float var = 0.f;
#pragma unroll
        for (int w = 0; w < 8; w++) { float d = y[w] - m; var = fmaf(d, d, var); }
        var *= 0.125f;
        float r = rsqrtf(var + 1e-5f);
        float xn[8];
#pragma unroll
        for (int w = 0; w < 8; w++) xn[w] = fmaf((y[w] - m) * r, cg1[w], cbe1[w]);

        float hh[8];
#pragma unroll
        for (int i2 = 0; i2 < 8; i2++) {
            float s = cb1[i2];
#pragma unroll
            for (int j = 0; j < 8; j++) s = fmaf(xn[j], cw1[i2 * 8 + j], s);
            hh[i2] = s;
        }

        float hq[8];
#pragma unroll
        for (int w = 0; w < 8; w++) a[w] = hh[w] + cwf[w];
        vqc8(a, hq);

        float z[8], m2 = 0.f;
#pragma unroll
        for (int i2 = 0; i2 < 8; i2++) {
            float s = cb2[i2];
#pragma unroll
            for (int j = 0; j < 8; j++) s = fmaf(hq[j], cw2[i2 * 8 + j], s);
            z[i2] = xn[i2] + s;
            m2 += z[i2];
        }
        m2 *= 0.125f;
        float v2 = 0.f;
#pragma unroll
        for (int i2 = 0; i2 < 8; i2++) { float d = z[i2] - m2; v2 = fmaf(d, d, v2); }
        v2 *= 0.125f;
        float r2 = rsqrtf(v2 + 1e-5f);
        float o[8];
#pragma unroll
        for (int i2 = 0; i2 < 8; i2++) o[i2] = fmaf((z[i2] - m2) * r2, cg2[i2], cbe2[i2]);

        float4* op = (float4*)(out + (size_t)tok * EGS);
        op[0] = make_float4(o[0], o[1], o[2], o[3]);
        op[1] = make_float4(o[4], o[5], o[6], o[7]);
    }
}

extern "C" void kernel_launch(void* const* d_in, const int* in_sizes, int n_in,
                              void* d_out, int out_size)
{
    const float* x   = (const float*)d_in[0];
    const float* Wq  = (const float*)d_in[1];
    const float* Wk  = (const float*)d_in[2];
    const float* Wv  = (const float*)d_in[3];
    const float* Wc  = (const float*)d_in[4];
    const float* Wf  = (const float*)d_in[5];
    const float* w1  = (const float*)d_in[6];
    const float* b1  = (const float*)d_in[7];
    const float* w2  = (const float*)d_in[8];
    const float* b2  = (const float*)d_in[9];
    const float* g1  = (const float*)d_in[10];
    const float* be1 = (const float*)d_in[11];
    const float* g2  = (const float*)d_in[12];
    const float* be2 = (const float*)d_in[13];
    float* out = (float*)d_out;

    const int ntok = in_sizes[0] / EGS;   // B*S
    const int nb   = ntok / SSEQ;         // B

    fused_kernel<<<nb * 2, 1024>>>(x, Wq, Wk, Wv, Wc, Wf, w1, b1, w2, b2,
                                   g1, be1, g2, be2, out);
}

// round 11
// speedup vs baseline: 3.6746x; 3.6746x over previous
#include <cuda_runtime.h>
#include <math.h>

// ---------------------------------------------------------------------------
// ViTBlockQuantum, fully fused. Analytic collapse of the 8-qubit VQC:
//   phi_w = in_w + theta_w;  z_k = prod_{w=0..k} cos(phi_w) (k>=1),
//   z_0 = prod_{w=1..7} cos(phi_w)
// One kernel: block = (batch, query-half), 1024 threads.
//   phase 1: K (thr 0-255), V (256-511), Q (512-639), consts (640+)
//   phase 2: thread = (query, k-eighth), BOTH heads; 2 keys x 2 heads/iter,
//            f32x2-packed, broadcast LDS
//   phase 3: kh==0 thread reduces partials and runs the tail for its own
//            query entirely in registers (no Ctx smem, 2 barriers total)
// ---------------------------------------------------------------------------

#define EGS 8
#define SSEQ 256
#define QH 128
// 0.5 (1/sqrt(dk), dk=4) * log2(e): folded into Q so softmax uses ex2 directly
#define QSCALE 0.72134752044448170368f

typedef unsigned long long u64;

__device__ __forceinline__ float ex2f(float x) {
    float y; asm("ex2.approx.ftz.f32 %0, %1;" : "=f"(y) : "f"(x)); return y;
}
__device__ __forceinline__ u64 pk2(float lo, float hi) {
    u64 r; asm("mov.b64 %0, {%1, %2};" : "=l"(r) : "f"(lo), "f"(hi)); return r;
}
__device__ __forceinline__ void upk2(float& lo, float& hi, u64 v) {
    asm("mov.b64 {%0, %1}, %2;" : "=f"(lo), "=f"(hi) : "l"(v));
}
__device__ __forceinline__ u64 mul2(u64 a, u64 b) {
    u64 d; asm("mul.rn.f32x2 %0, %1, %2;" : "=l"(d) : "l"(a), "l"(b)); return d;
}
__device__ __forceinline__ u64 fma2(u64 a, u64 b, u64 c) {
    u64 d; asm("fma.rn.f32x2 %0, %1, %2, %3;" : "=l"(d) : "l"(a), "l"(b), "l"(c)); return d;
}
__device__ __forceinline__ u64 add2(u64 a, u64 b) {
    u64 d; asm("add.rn.f32x2 %0, %1, %2;" : "=l"(d) : "l"(a), "l"(b)); return d;
}

__device__ __forceinline__ void vqc8(const float a[8], float z[8]) {
    float c[8];
#pragma unroll
    for (int w = 0; w < 8; w++) c[w] = __cosf(a[w]);
    float p = c[0];
#pragma unroll
    for (int k = 1; k < 8; k++) { p *= c[k]; z[k] = p; }
    float q = c[1];
#pragma unroll
    for (int w = 2; w < 8; w++) q *= c[w];
    z[0] = q;
}

// paired K/V smem layout: keys 2k,2k+1 interleaved; key-pair kp = 4 ulonglong2:
//   u2#(kp*4 + h*2 + j) = packed (dim 2j, dim 2j+1) f32x2 pairs for head h
__device__ __forceinline__ int kvidx(int k, int d) {
    return (k >> 1) * 16 + (d >> 2) * 8 + ((d & 2) << 1) + ((d & 1) << 1) + (k & 1);
}

#define PSTRIDE 11   // floats per Part unit (10 used + 1 pad -> conflict-free)

__global__ void __launch_bounds__(1024, 1) fused_kernel(
    const float* __restrict__ x,
    const float* __restrict__ Wq, const float* __restrict__ Wk,
    const float* __restrict__ Wv, const float* __restrict__ Wc,
    const float* __restrict__ Wf,
    const float* __restrict__ w1, const float* __restrict__ b1,
    const float* __restrict__ w2, const float* __restrict__ b2,
    const float* __restrict__ g1, const float* __restrict__ be1,
    const float* __restrict__ g2, const float* __restrict__ be2,
    float* __restrict__ out)
{
    __shared__ __align__(16) float Ks[SSEQ * 8];
    __shared__ __align__(16) float Vs[SSEQ * 8];
    __shared__ __align__(16) float Qs[QH * 8];
    __shared__ float Part[7 * QH * PSTRIDE];   // kh = 1..7 partials
    __shared__ float cw1[64], cw2[64];
    __shared__ float cb1[8], cb2[8], cwc[8], cwf[8];
    __shared__ float cg1[8], cbe1[8], cg2[8], cbe2[8];

    const int b   = blockIdx.x >> 1;
    const int qh  = blockIdx.x & 1;
    const int tid = threadIdx.x;

    // ---------------- phase 1: QKV + constant staging (parallel groups) ------
    if (tid < 512) {
        const int t = tid & 255;
        const int isV = tid >> 8;
        const float* W = isV ? Wv : Wk;
        const float4* xt = (const float4*)(x + (size_t)(b * SSEQ + t) * EGS);
        float4 x0 = xt[0], x1 = xt[1];
        float a[8], z[8];
        a[0] = x0.x + __ldg(W + 0); a[1] = x0.y + __ldg(W + 1);
        a[2] = x0.z + __ldg(W + 2); a[3] = x0.w + __ldg(W + 3);
        a[4] = x1.x + __ldg(W + 4); a[5] = x1.y + __ldg(W + 5);
        a[6] = x1.z + __ldg(W + 6); a[7] = x1.w + __ldg(W + 7);
        vqc8(a, z);
        float* dst = isV ? Vs : Ks;
#pragma unroll
        for (int d = 0; d < 8; d++) dst[kvidx(t, d)] = z[d];
    } else if (tid < 640) {
        const int i = tid - 512;
        const float4* xt = (const float4*)(x + (size_t)(b * SSEQ + qh * QH + i) * EGS);
        float4 x0 = xt[0], x1 = xt[1];
        float a[8], z[8];
        a[0] = x0.x + __ldg(Wq + 0); a[1] = x0.y + __ldg(Wq + 1);
        a[2] = x0.z + __ldg(Wq + 2); a[3] = x0.w + __ldg(Wq + 3);
        a[4] = x1.x + __ldg(Wq + 4); a[5] = x1.y + __ldg(Wq + 5);
        a[6] = x1.z + __ldg(Wq + 6); a[7] = x1.w + __ldg(Wq + 7);
        vqc8(a, z);
#pragma unroll
        for (int d = 0; d < 8; d++) Qs[i * 8 + d] = z[d] * QSCALE;
    } else {
        const int j = tid - 640;
        if (j < 64) { cw1[j] = w1[j]; cw2[j] = w2[j]; }
        else if (j < 72) {
            const int k = j - 64;
            cb1[k] = b1[k];  cb2[k] = b2[k];
            cwc[k] = Wc[k];  cwf[k] = Wf[k];
            cg1[k] = g1[k];  cbe1[k] = be1[k];
            cg2[k] = g2[k];  cbe2[k] = be2[k];
        }
    }
    __syncthreads();

    // ------------- phase 2: attention, (query, kh), both heads ---------------
    const int i  = tid & 127;          // local query
    const int kh = tid >> 7;           // k-eighth (0..7)

    float vals[10];                    // sum_h0, c_h0[4], sum_h1, c_h1[4]
    {
        float4 qv0 = *(const float4*)&Qs[i * 8];
        float4 qv1 = *(const float4*)&Qs[i * 8 + 4];
        u64 q00 = pk2(qv0.x, qv0.x), q01 = pk2(qv0.y, qv0.y);
        u64 q02 = pk2(qv0.z, qv0.z), q03 = pk2(qv0.w, qv0.w);
        u64 q10 = pk2(qv1.x, qv1.x), q11 = pk2(qv1.y, qv1.y);
        u64 q12 = pk2(qv1.z, qv1.z), q13 = pk2(qv1.w, qv1.w);

        const ulonglong2* Kp = (const ulonglong2*)Ks + (kh << 6);
        const ulonglong2* Vp = (const ulonglong2*)Vs + (kh << 6);

        u64 sum0 = 0ull, c00 = 0ull, c01 = 0ull, c02 = 0ull, c03 = 0ull;
        u64 sum1 = 0ull, c10 = 0ull, c11 = 0ull, c12 = 0ull, c13 = 0ull;
#pragma unroll 8
        for (int kp = 0; kp < 16; kp++) {
            ulonglong2 k0 = Kp[kp * 4],     k1 = Kp[kp * 4 + 1];
            ulonglong2 k2 = Kp[kp * 4 + 2], k3 = Kp[kp * 4 + 3];
            u64 s0 = mul2(q00, k0.x);
            u64 s1 = mul2(q10, k2.x);
            s0 = fma2(q01, k0.y, s0);
            s1 = fma2(q11, k2.y, s1);
            s0 = fma2(q02, k1.x, s0);
            s1 = fma2(q12, k3.x, s1);
            s0 = fma2(q03, k1.y, s0);
            s1 = fma2(q13, k3.y, s1);
            float l0, h0, l1, h1;
            upk2(l0, h0, s0);
            upk2(l1, h1, s1);
            u64 pp0 = pk2(ex2f(l0), ex2f(h0));
            u64 pp1 = pk2(ex2f(l1), ex2f(h1));
            ulonglong2 v0 = Vp[kp * 4],     v1 = Vp[kp * 4 + 1];
            ulonglong2 v2 = Vp[kp * 4 + 2], v3 = Vp[kp * 4 + 3];
            sum0 = add2(sum0, pp0);
            sum1 = add2(sum1, pp1);
            c00 = fma2(pp0, v0.x, c00);
            c10 = fma2(pp1, v2.x, c10);
            c01 = fma2(pp0, v0.y, c01);
            c11 = fma2(pp1, v2.y, c11);
            c02 = fma2(pp0, v1.x, c02);
            c12 = fma2(pp1, v3.x, c12);
            c03 = fma2(pp0, v1.y, c03);
            c13 = fma2(pp1, v3.y, c13);
        }
        { float l, hx; upk2(l, hx, sum0); vals[0] = l + hx; }
        { float l, hx; upk2(l, hx, c00);  vals[1] = l + hx; }
        { float l, hx; upk2(l, hx, c01);  vals[2] = l + hx; }
        { float l, hx; upk2(l, hx, c02);  vals[3] = l + hx; }
        { float l, hx; upk2(l, hx, c03);  vals[4] = l + hx; }
        { float l, hx; upk2(l, hx, sum1); vals[5] = l + hx; }
        { float l, hx; upk2(l, hx, c10);  vals[6] = l + hx; }
        { float l, hx; upk2(l, hx, c11);  vals[7] = l + hx; }
        { float l, hx; upk2(l, hx, c12);  vals[8] = l + hx; }
        { float l, hx; upk2(l, hx, c13);  vals[9] = l + hx; }
    }

    if (kh != 0) {
        float* pr = &Part[((kh - 1) * QH + i) * PSTRIDE];
#pragma unroll
        for (int j = 0; j < 10; j++) pr[j] = vals[j];
    }
    __syncthreads();

    // ------------- phase 3: kh==0 reduces + runs tail in registers -----------
    if (kh == 0) {
#pragma unroll
        for (int r = 0; r < 7; r++) {
            const float* pr = &Part[(r * QH + i) * PSTRIDE];
#pragma unroll
            for (int j = 0; j < 10; j++) vals[j] += pr[j];
        }
        const int tok = b * SSEQ + qh * QH + i;
        // x reload: lines are L1-warm (phase 1 touched every token of batch b)
        const float4* xt = (const float4*)(x + (size_t)tok * EGS);
        float4 x0 = xt[0], x1 = xt[1];
        float xi[8] = {x0.x, x0.y, x0.z, x0.w, x1.x, x1.y, x1.z, x1.w};

        float inv0 = __fdividef(1.f, vals[0]);
        float inv1 = __fdividef(1.f, vals[5]);
        float a[8], ao[8];
        a[0] = vals[1] * inv0 + cwc[0]; a[1] = vals[2] * inv0 + cwc[1];
        a[2] = vals[3] * inv0 + cwc[2]; a[3] = vals[4] * inv0 + cwc[3];
        a[4] = vals[6] * inv1 + cwc[4]; a[5] = vals[7] * inv1 + cwc[5];
        a[6] = vals[8] * inv1 + cwc[6]; a[7] = vals[9] * inv1 + cwc[7];
        vqc8(a, ao);

        float y[8], m = 0.f;
#pragma unroll
        for (int w = 0; w < 8; w++) { y[w] = xi[w] + ao[w]; m += y[w]; }
        m *= 0.125f;
        float var = 0.f;
#pragma unroll
        for (int w = 0; w < 8; w++) { float d = y[w] - m; var = fmaf(d, d, var); }
        var *= 0.125f;
        float r = rsqrtf(var + 1e-5f);
        float xn[8];
#pragma unroll
        for (int w = 0; w < 8; w++) xn[w] = fmaf((y[w] - m) * r, cg1[w], cbe1[w]);

        float hh[8];
#pragma unroll
        for (int i2 = 0; i2 < 8; i2++) {
            float s = cb1[i2];
#pragma unroll
            for (int j = 0; j < 8; j++) s = fmaf(xn[j], cw1[i2 * 8 + j], s);
            hh[i2] = s;
        }

        float hq[8];
#pragma unroll
        for (int w = 0; w < 8; w++) a[w] = hh[w] + cwf[w];
        vqc8(a, hq);

        float z[8], m2 = 0.f;
#pragma unroll
        for (int i2 = 0; i2 < 8; i2++) {
            float s = cb2[i2];
#pragma unroll
            for (int j = 0; j < 8; j++) s = fmaf(hq[j], cw2[i2 * 8 + j], s);
            z[i2] = xn[i2] + s;
            m2 += z[i2];
        }
        m2 *= 0.125f;
        float v2 = 0.f;
#pragma unroll
        for (int i2 = 0; i2 < 8; i2++) { float d = z[i2] - m2; v2 = fmaf(d, d, v2); }
        v2 *= 0.125f;
        float r2 = rsqrtf(v2 + 1e-5f);
        float o[8];
#pragma unroll
        for (int i2 = 0; i2 < 8; i2++) o[i2] = fmaf((z[i2] - m2) * r2, cg2[i2], cbe2[i2]);

        float4* op = (float4*)(out + (size_t)tok * EGS);
        op[0] = make_float4(o[0], o[1], o[2], o[3]);
        op[1] = make_float4(o[4], o[5], o[6], o[7]);
    }
}

extern "C" void kernel_launch(void* const* d_in, const int* in_sizes, int n_in,
                              void* d_out, int out_size)
{
    const float* x   = (const float*)d_in[0];
    const float* Wq  = (const float*)d_in[1];
    const float* Wk  = (const float*)d_in[2];
    const float* Wv  = (const float*)d_in[3];
    const float* Wc  = (const float*)d_in[4];
    const float* Wf  = (const float*)d_in[5];
    const float* w1  = (const float*)d_in[6];
    const float* b1  = (const float*)d_in[7];
    const float* w2  = (const float*)d_in[8];
    const float* b2  = (const float*)d_in[9];
    const float* g1  = (const float*)d_in[10];
    const float* be1 = (const float*)d_in[11];
    const float* g2  = (const float*)d_in[12];
    const float* be2 = (const float*)d_in[13];
    float* out = (float*)d_out;

    const int ntok = in_sizes[0] / EGS;   // B*S
    const int nb   = ntok / SSEQ;         // B

    fused_kernel<<<nb * 2, 1024>>>(x, Wq, Wk, Wv, Wc, Wf, w1, b1, w2, b2,
                                   g1, be1, g2, be2, out);
}

// round 13
// speedup vs baseline: 4.5424x; 1.2362x over previous
#include <cuda_runtime.h>
#include <cuda_fp16.h>
#include <math.h>
#include <stdint.h>

// ---------------------------------------------------------------------------
// ViTBlockQuantum via mma.sync (HMMA) tensor cores. VQC collapsed analytically.
// GEMM1: scores[128x512] = Q[128x8] x Khead[8x512]  (m16n8k8, head-masked K)
// exp on MUFU, P stays in registers as GEMM2 A-fragments (flash-attn reuse)
// GEMM2: [ctx|den][128x16] = P[128x512] x W[512x16]  (m16n8k16)
// ---------------------------------------------------------------------------

#define EGS 8
#define SSEQ 256
#define QH 128
#define QSCALE 0.72134752044448170368f   // 0.5 * log2(e)

// dynamic smem offsets (bytes)
#define QS   0        // Q fp16 [128 x 8]                   2048 B
#define KH   2048     // K fp16 head-masked [512 cols x 8]  8192 B
#define WD   10240    // W fp16 [16 ctx-cols x 520 k]       16640 B
#define RED  26880    // partial ctx f32 [4][128][11]       22528 B
#define SMEM_REQ 49408

static __device__ __forceinline__ float ex2f(float x) {
    float y; asm("ex2.approx.ftz.f32 %0, %1;" : "=f"(y) : "f"(x)); return y;
}
static __device__ __forceinline__ uint32_t pkh2(float hi, float lo) {
    uint32_t u; asm("cvt.rn.f16x2.f32 %0, %1, %2;" : "=r"(u) : "f"(hi), "f"(lo));
    return u;
}
static __device__ __forceinline__ uint32_t lds32(uint32_t a) {
    uint32_t v; asm volatile("ld.shared.b32 %0, [%1];" : "=r"(v) : "r"(a));
    return v;
}
static __device__ __forceinline__ void sts128(uint32_t a, uint32_t r0, uint32_t r1,
                                              uint32_t r2, uint32_t r3) {
    asm volatile("st.shared.v4.b32 [%0], {%1, %2, %3, %4};"
                 :: "r"(a), "r"(r0), "r"(r1), "r"(r2), "r"(r3) : "memory");
}
static __device__ __forceinline__ void sts16(uint32_t a, unsigned short v) {
    asm volatile("st.shared.u16 [%0], %1;" :: "r"(a), "h"(v) : "memory");
}

// D = A(16x8) * B(8x8) row.col, f32 accum from zero
static __device__ __forceinline__ void mma1688(float* d, uint32_t a0, uint32_t a1,
                                               uint32_t b0) {
    asm volatile(
        "mma.sync.aligned.m16n8k8.row.col.f32.f16.f16.f32 "
        "{%0,%1,%2,%3}, {%4,%5}, {%6}, {%7,%8,%9,%10};"
        : "=f"(d[0]), "=f"(d[1]), "=f"(d[2]), "=f"(d[3])
        : "r"(a0), "r"(a1), "r"(b0),
          "f"(0.f), "f"(0.f), "f"(0.f), "f"(0.f));
}
// D += A(16x16) * B(16x8) row.col, accumulate in place
static __device__ __forceinline__ void mma16816(float* d, const uint32_t* a,
                                                uint32_t b0, uint32_t b1) {
    asm volatile(
        "mma.sync.aligned.m16n8k16.row.col.f32.f16.f16.f32 "
        "{%0,%1,%2,%3}, {%4,%5,%6,%7}, {%8,%9}, {%0,%1,%2,%3};"
        : "+f"(d[0]), "+f"(d[1]), "+f"(d[2]), "+f"(d[3])
        : "r"(a[0]), "r"(a[1]), "r"(a[2]), "r"(a[3]), "r"(b0), "r"(b1));
}

static __device__ __forceinline__ void vqc8(const float a[8], float z[8]) {
    float c[8];
#pragma unroll
    for (int w = 0; w < 8; w++) c[w] = __cosf(a[w]);
    float p = c[0];
#pragma unroll
    for (int k = 1; k < 8; k++) { p *= c[k]; z[k] = p; }
    float q = c[1];
#pragma unroll
    for (int w = 2; w < 8; w++) q *= c[w];
    z[0] = q;
}

__global__ void __launch_bounds__(1024, 1) fused_mma_kernel(
    const float* __restrict__ x,
    const float* __restrict__ Wq, const float* __restrict__ Wk,
    const float* __restrict__ Wv, const float* __restrict__ Wc,
    const float* __restrict__ Wf,
    const float* __restrict__ w1, const float* __restrict__ b1,
    const float* __restrict__ w2, const float* __restrict__ b2,
    const float* __restrict__ g1, const float* __restrict__ be1,
    const float* __restrict__ g2, const float* __restrict__ be2,
    float* __restrict__ out)
{
    extern __shared__ __align__(16) char dynsm[];
    const uint32_t sb = (uint32_t)__cvta_generic_to_shared(dynsm);
    float* redf = (float*)(dynsm + RED);

    const int b    = blockIdx.x >> 1;
    const int qh   = blockIdx.x & 1;
    const int tid  = threadIdx.x;
    const int wid  = tid >> 5;
    const int lane = tid & 31;

    // ---------------- phase 1: stage Q / masked-K / W tiles (fp16) ----------
    if (tid < 256) {                        // K for token t -> 2 masked cols
        const int t = tid;
        const float4* xt = (const float4*)(x + (size_t)(b * SSEQ + t) * EGS);
        float4 x0 = xt[0], x1 = xt[1];
        float a[8], z[8];
        a[0] = x0.x + __ldg(Wk + 0); a[1] = x0.y + __ldg(Wk + 1);
        a[2] = x0.z + __ldg(Wk + 2); a[3] = x0.w + __ldg(Wk + 3);
        a[4] = x1.x + __ldg(Wk + 4); a[5] = x1.y + __ldg(Wk + 5);
        a[6] = x1.z + __ldg(Wk + 6); a[7] = x1.w + __ldg(Wk + 7);
        vqc8(a, z);
        // col t (head0): dims 0-3 in rows 0-3, rows 4-7 zero
        sts128(sb + KH + t * 16,
               pkh2(z[1], z[0]), pkh2(z[3], z[2]), 0u, 0u);
        // col 256+t (head1): rows 0-3 zero, dims 4-7 in rows 4-7
        sts128(sb + KH + (256 + t) * 16,
               0u, 0u, pkh2(z[5], z[4]), pkh2(z[7], z[6]));
    } else if (tid < 512) {                 // V for token t -> W cols
        const int t = tid - 256;
        const float4* xt = (const float4*)(x + (size_t)(b * SSEQ + t) * EGS);
        float4 x0 = xt[0], x1 = xt[1];
        float a[8], z[8];
        a[0] = x0.x + __ldg(Wv + 0); a[1] = x0.y + __ldg(Wv + 1);
        a[2] = x0.z + __ldg(Wv + 2); a[3] = x0.w + __ldg(Wv + 3);
        a[4] = x1.x + __ldg(Wv + 4); a[5] = x1.y + __ldg(Wv + 5);
        a[6] = x1.z + __ldg(Wv + 6); a[7] = x1.w + __ldg(Wv + 7);
        vqc8(a, z);
        // W[c][k]: k=t (h0 rows): c0-3 = z0-3, c8 = 1, rest 0
        //          k=256+t (h1 rows): c4-7 = z4-7, c9 = 1, rest 0
#pragma unroll
        for (int c = 0; c < 16; c++) {
            float v0 = (c < 4) ? z[c] : (c == 8 ? 1.f : 0.f);
            float v1 = (c >= 4 && c < 8) ? z[c] : (c == 9 ? 1.f : 0.f);
            __half h0 = __float2half_rn(v0);
            __half h1 = __float2half_rn(v1);
            sts16(sb + WD + (c * 520 + t) * 2,       __half_as_ushort(h0));
            sts16(sb + WD + (c * 520 + 256 + t) * 2, __half_as_ushort(h1));
        }
    } else if (tid < 640) {                 // Q for query i (QSCALE folded)
        const int i = tid - 512;
        const float4* xt = (const float4*)(x + (size_t)(b * SSEQ + qh * QH + i) * EGS);
        float4 x0 = xt[0], x1 = xt[1];
        float a[8], z[8];
        a[0] = x0.x + __ldg(Wq + 0); a[1] = x0.y + __ldg(Wq + 1);
        a[2] = x0.z + __ldg(Wq + 2); a[3] = x0.w + __ldg(Wq + 3);
        a[4] = x1.x + __ldg(Wq + 4); a[5] = x1.y + __ldg(Wq + 5);
        a[6] = x1.z + __ldg(Wq + 6); a[7] = x1.w + __ldg(Wq + 7);
        vqc8(a, z);
#pragma unroll
        for (int d = 0; d < 8; d++) z[d] *= QSCALE;
        sts128(sb + QS + i * 16,
               pkh2(z[1], z[0]), pkh2(z[3], z[2]),
               pkh2(z[5], z[4]), pkh2(z[7], z[6]));
    }
    __syncthreads();

    // ---------------- GEMM phase: all 32 warps ----------------
    {
        const int mt = wid >> 2;            // m-tile (16 queries)
        const int ng = wid & 3;             // k-group / n-range
        const int g  = lane >> 2;
        const int t  = lane & 3;

        // A-frag for GEMM1 (Q rows mt*16+g, +8; cols 2t,2t+1)
        const uint32_t a0 = lds32(sb + QS + (mt * 16 + g) * 16 + 4 * t);
        const uint32_t a1 = lds32(sb + QS + (mt * 16 + g + 8) * 16 + 4 * t);

        float c2a[4] = {0.f, 0.f, 0.f, 0.f};   // ctx cols 0-7
        float c2b[4] = {0.f, 0.f, 0.f, 0.f};   // ctx cols 8-15 (8,9 = denoms)

#pragma unroll
        for (int ch = 0; ch < 8; ch++) {
            uint32_t pa[4];
#pragma unroll
            for (int sub = 0; sub < 2; sub++) {
                const int nt = ng * 16 + ch * 2 + sub;   // GEMM1 n-tile
                uint32_t b0 = lds32(sb + KH + (nt * 8 + g) * 16 + 4 * t);
                float d[4];
                mma1688(d, a0, a1, b0);
                pa[sub * 2 + 0] = pkh2(ex2f(d[1]), ex2f(d[0]));
                pa[sub * 2 + 1] = pkh2(ex2f(d[3]), ex2f(d[2]));
            }
            const int k0 = ng * 128 + ch * 16;
            {   // ctx n-tile 0 (cols 0-7)
                uint32_t b0 = lds32(sb + WD + (g * 520 + k0 + 2 * t) * 2);
                uint32_t b1 = lds32(sb + WD + (g * 520 + k0 + 8 + 2 * t) * 2);
                mma16816(c2a, pa, b0, b1);
            }
            {   // ctx n-tile 1 (cols 8-15)
                uint32_t b0 = lds32(sb + WD + ((8 + g) * 520 + k0 + 2 * t) * 2);
                uint32_t b1 = lds32(sb + WD + ((8 + g) * 520 + k0 + 8 + 2 * t) * 2);
                mma16816(c2b, pa, b0, b1);
            }
        }

        // scatter partial ctx to Red[ng][q][c] (cols 0-9 only)
        const int q0 = mt * 16 + g;
        float* rp  = redf + (ng * 128 + q0) * 11;
        float* rp8 = rp + 8 * 11;
        rp[2 * t]      = c2a[0];
        rp[2 * t + 1]  = c2a[1];
        rp8[2 * t]     = c2a[2];
        rp8[2 * t + 1] = c2a[3];
        if (t == 0) {
            rp[8]  = c2b[0];  rp[9]  = c2b[1];
            rp8[8] = c2b[2];  rp8[9] = c2b[3];
        }
    }
    __syncthreads();

    // ---------------- tail: one thread per query ----------------
    if (tid < QH) {
        const int q = tid;
        float v[10];
#pragma unroll
        for (int c = 0; c < 10; c++)
            v[c] = redf[q * 11 + c] + redf[(128 + q) * 11 + c]
                 + redf[(256 + q) * 11 + c] + redf[(384 + q) * 11 + c];

        const int tok = b * SSEQ + qh * QH + q;
        const float4* xt = (const float4*)(x + (size_t)tok * EGS);
        float4 x0 = xt[0], x1 = xt[1];
        float xi[8] = {x0.x, x0.y, x0.z, x0.w, x1.x, x1.y, x1.z, x1.w};

        float inv0 = __fdividef(1.f, v[8]);
        float inv1 = __fdividef(1.f, v[9]);
        float a[8], ao[8];
        a[0] = v[0] * inv0 + __ldg(Wc + 0); a[1] = v[1] * inv0 + __ldg(Wc + 1);
        a[2] = v[2] * inv0 + __ldg(Wc + 2); a[3] = v[3] * inv0 + __ldg(Wc + 3);
        a[4] = v[4] * inv1 + __ldg(Wc + 4); a[5] = v[5] * inv1 + __ldg(Wc + 5);
        a[6] = v[6] * inv1 + __ldg(Wc + 6); a[7] = v[7] * inv1 + __ldg(Wc + 7);
        vqc8(a, ao);

        float y[8], m = 0.f;
#pragma unroll
        for (int w = 0; w < 8; w++) { y[w] = xi[w] + ao[w]; m += y[w]; }
        m *= 0.125f;
        float var = 0.f;
#pragma unroll
        for (int w = 0; w < 8; w++) { float d = y[w] - m; var = fmaf(d, d, var); }
        var *= 0.125f;
        float r = rsqrtf(var + 1e-5f);
        float xn[8];
#pragma unroll
        for (int w = 0; w < 8; w++)
            xn[w] = fmaf((y[w] - m) * r, __ldg(g1 + w), __ldg(be1 + w));

        float hh[8];
#pragma unroll
        for (int i2 = 0; i2 < 8; i2++) {
            float s = __ldg(b1 + i2);
#pragma unroll
            for (int j = 0; j < 8; j++) s = fmaf(xn[j], __ldg(w1 + i2 * 8 + j), s);
            hh[i2] = s;
        }

        float hq[8];
#pragma unroll
        for (int w = 0; w < 8; w++) a[w] = hh[w] + __ldg(Wf + w);
        vqc8(a, hq);

        float z[8], m2 = 0.f;
#pragma unroll
        for (int i2 = 0; i2 < 8; i2++) {
            float s = __ldg(b2 + i2);
#pragma unroll
            for (int j = 0; j < 8; j++) s = fmaf(hq[j], __ldg(w2 + i2 * 8 + j), s);
            z[i2] = xn[i2] + s;
            m2 += z[i2];
        }
        m2 *= 0.125f;
        float v2 = 0.f;
#pragma unroll
        for (int i2 = 0; i2 < 8; i2++) { float d = z[i2] - m2; v2 = fmaf(d, d, v2); }
        v2 *= 0.125f;
        float r2 = rsqrtf(v2 + 1e-5f);
        float o[8];
#pragma unroll
        for (int i2 = 0; i2 < 8; i2++)
            o[i2] = fmaf((z[i2] - m2) * r2, __ldg(g2 + i2), __ldg(be2 + i2));

        float4* op = (float4*)(out + (size_t)tok * EGS);
        op[0] = make_float4(o[0], o[1], o[2], o[3]);
        op[1] = make_float4(o[4], o[5], o[6], o[7]);
    }
}

extern "C" void kernel_launch(void* const* d_in, const int* in_sizes, int n_in,
                              void* d_out, int out_size)
{
    const float* x   = (const float*)d_in[0];
    const float* Wq  = (const float*)d_in[1];
    const float* Wk  = (const float*)d_in[2];
    const float* Wv  = (const float*)d_in[3];
    const float* Wc  = (const float*)d_in[4];
    const float* Wf  = (const float*)d_in[5];
    const float* w1  = (const float*)d_in[6];
    const float* b1  = (const float*)d_in[7];
    const float* w2  = (const float*)d_in[8];
    const float* b2  = (const float*)d_in[9];
    const float* g1  = (const float*)d_in[10];
    const float* be1 = (const float*)d_in[11];
    const float* g2  = (const float*)d_in[12];
    const float* be2 = (const float*)d_in[13];
    float* out = (float*)d_out;

    const int ntok = in_sizes[0] / EGS;   // B*S
    const int nb   = ntok / SSEQ;         // B

    cudaFuncSetAttribute(fused_mma_kernel,
                         cudaFuncAttributeMaxDynamicSharedMemorySize, SMEM_REQ);
    fused_mma_kernel<<<nb * 2, 1024, SMEM_REQ>>>(x, Wq, Wk, Wv, Wc, Wf,
                                                 w1, b1, w2, b2,
                                                 g1, be1, g2, be2, out);
}